// round 9
// baseline (speedup 1.0000x reference)
#include <cuda_runtime.h>
#include <cuda_bf16.h>
#include <math.h>
#include <stdint.h>

// Problem shapes (fixed)
#define G_  8
#define E_  8
#define C_  512
#define H_  1024
#define F_  4096
#define M_  (G_ * C_)    // 4096 rows per expert

#define BM 128
#define BN 128
#define BK 32
#define AS_STRIDE (BK + 8)   // 40 bf16 = 80B rows  -> ldmatrix conflict-free
#define BS_STRIDE (BN + 8)   // 136 bf16 = 272B rows -> ldmatrix conflict-free

#define A_ELEMS     (BM * AS_STRIDE)              // 5120 bf16
#define B_ELEMS     (BK * BS_STRIDE)              // 4352 bf16
#define STAGE_ELEMS (2 * A_ELEMS + 2 * B_ELEMS)   // 18944 bf16 = 37888 B
#define NSTAGE      4
#define SMEM_BYTES  (NSTAGE * STAGE_ELEMS * 2)    // 151552 B

// ---- pre-split global operands (static device scratch; no cudaMalloc) ----
__device__ __align__(16) __nv_bfloat16 g_in_hi[(size_t)G_ * E_ * C_ * H_];
__device__ __align__(16) __nv_bfloat16 g_in_lo[(size_t)G_ * E_ * C_ * H_];
__device__ __align__(16) __nv_bfloat16 g_wi_hi[(size_t)E_ * H_ * F_];
__device__ __align__(16) __nv_bfloat16 g_wi_lo[(size_t)E_ * H_ * F_];
__device__ __align__(16) __nv_bfloat16 g_wo_hi[(size_t)E_ * F_ * H_];
__device__ __align__(16) __nv_bfloat16 g_wo_lo[(size_t)E_ * F_ * H_];
__device__ __align__(16) __nv_bfloat16 g_scr_hi[(size_t)E_ * M_ * F_];
__device__ __align__(16) __nv_bfloat16 g_scr_lo[(size_t)E_ * M_ * F_];

__device__ __forceinline__ float gelu_exact(float x) {
    return 0.5f * x * (1.0f + erff(x * 0.70710678118654752440f));
}

__device__ __forceinline__ uint32_t pack2(__nv_bfloat16 a, __nv_bfloat16 b) {
    __nv_bfloat162 t = __halves2bfloat162(a, b);
    return *reinterpret_cast<uint32_t*>(&t);
}

__device__ __forceinline__ void split_bf16(float x, __nv_bfloat16& h, __nv_bfloat16& l) {
    h = __float2bfloat16_rn(x);
    l = __float2bfloat16_rn(x - __bfloat162float(h));
}

__device__ __forceinline__ uint32_t smem_u32(const void* p) {
    return (uint32_t)__cvta_generic_to_shared(p);
}

__device__ __forceinline__ void cp16(uint32_t dst, const void* src) {
    asm volatile("cp.async.cg.shared.global [%0], [%1], 16;\n" :: "r"(dst), "l"(src));
}

__device__ __forceinline__ void ldmatrix_x4(uint32_t* r, uint32_t addr) {
    asm volatile("ldmatrix.sync.aligned.m8n8.x4.shared.b16 {%0,%1,%2,%3}, [%4];"
                 : "=r"(r[0]), "=r"(r[1]), "=r"(r[2]), "=r"(r[3]) : "r"(addr));
}

__device__ __forceinline__ void ldmatrix_x2t(uint32_t* r, uint32_t addr) {
    asm volatile("ldmatrix.sync.aligned.m8n8.x2.trans.shared.b16 {%0,%1}, [%2];"
                 : "=r"(r[0]), "=r"(r[1]) : "r"(addr));
}

__device__ __forceinline__ void mma_bf16(float* d, const uint32_t* a, const uint32_t* b) {
    asm volatile(
        "mma.sync.aligned.m16n8k16.row.col.f32.bf16.bf16.f32 "
        "{%0,%1,%2,%3}, {%4,%5,%6,%7}, {%8,%9}, {%0,%1,%2,%3};\n"
        : "+f"(d[0]), "+f"(d[1]), "+f"(d[2]), "+f"(d[3])
        : "r"(a[0]), "r"(a[1]), "r"(a[2]), "r"(a[3]),
          "r"(b[0]), "r"(b[1]));
}

// ---------------------------------------------------------------------------
// Pre-split: fp32 -> (hi, lo) bf16 arrays, vectorized x4.
// ---------------------------------------------------------------------------
__global__ __launch_bounds__(256)
void split_kernel(const float4* __restrict__ src,
                  uint2* __restrict__ hi, uint2* __restrict__ lo, int n4)
{
    int i = blockIdx.x * blockDim.x + threadIdx.x;
    if (i >= n4) return;
    float4 v = src[i];
    __nv_bfloat16 h0, h1, h2, h3, l0, l1, l2, l3;
    split_bf16(v.x, h0, l0); split_bf16(v.y, h1, l1);
    split_bf16(v.z, h2, l2); split_bf16(v.w, h3, l3);
    hi[i] = make_uint2(pack2(h0, h1), pack2(h2, h3));
    lo[i] = make_uint2(pack2(l0, l1), pack2(l2, l3));
}

// ---------------------------------------------------------------------------
// bf16x3 GEMM on pre-split operands, 4-stage cp.async pipeline:
//   D[M,N] = A[M,K] @ B[K,N] (+bias; G1: exact GELU + split-store to scratch)
// A row-major (row stride Kdim), B row-major (row stride Ndim), both bf16 hi/lo.
// G1: A = split inputs (g/e interleaved base), D = split scratch.
// G2: A = split scratch, D = fp32 out (g/e interleaved base).
// 128 | C so tile rows never cross a g-boundary.
// ---------------------------------------------------------------------------
template<bool G1>
__global__ __launch_bounds__(256)
void ffn_mma(const __nv_bfloat16* __restrict__ Ahi_g0,
             const __nv_bfloat16* __restrict__ Alo_g0,
             const __nv_bfloat16* __restrict__ Bhi_g0,
             const __nv_bfloat16* __restrict__ Blo_g0,
             const float* __restrict__ bias,
             float* __restrict__ Dout,          // G2 only
             __nv_bfloat16* __restrict__ Dhi,   // G1 only
             __nv_bfloat16* __restrict__ Dlo,   // G1 only
             int Kdim, int Ndim)
{
    extern __shared__ __nv_bfloat16 smem[];

    const int e   = blockIdx.z;
    const int bm  = blockIdx.y * BM;
    const int bn  = blockIdx.x * BN;
    const int tid = threadIdx.x;
    const int lane = tid & 31;
    const int wid  = tid >> 5;
    const int gid  = lane >> 2;
    const int tig  = lane & 3;

    // A base pointers for this CTA's 128 rows (row stride = Kdim)
    size_t a_off;
    if (G1) {
        const int g = bm >> 9;            // / C_
        const int c = bm & (C_ - 1);
        a_off = ((size_t)(g * E_ + e) * C_ + c) * Kdim;
    } else {
        a_off = ((size_t)e * M_ + bm) * (size_t)Kdim;
    }
    const __nv_bfloat16* Ahi_g = Ahi_g0 + a_off;
    const __nv_bfloat16* Alo_g = Alo_g0 + a_off;
    const size_t b_off = (size_t)e * Kdim * Ndim + bn;
    const __nv_bfloat16* Bhi_g = Bhi_g0 + b_off;
    const __nv_bfloat16* Blo_g = Blo_g0 + b_off;

    // warp tile: 2 (M) x 4 (N) warps, 64x32 each
    const int wm = (wid >> 2) * 64;
    const int wn = (wid & 3) * 32;

    float acc[4][4][4];
#pragma unroll
    for (int i = 0; i < 4; i++)
#pragma unroll
        for (int j = 0; j < 4; j++)
#pragma unroll
            for (int k = 0; k < 4; k++) acc[i][j][k] = 0.0f;

    // cp.async loader: 16B chunks (8 bf16). Per stage: A = 512 chunks
    // (128 rows x 4 k-chunks), B = 512 chunks (32 rows x 16 n-chunks);
    // 256 threads x 2 rounds cover each, x4 arrays (Ahi/Alo/Bhi/Blo).
    auto issue_stage = [&](int st, int kt) {
        __nv_bfloat16* sAhi = smem + st * STAGE_ELEMS;
        __nv_bfloat16* sAlo = sAhi + A_ELEMS;
        __nv_bfloat16* sBhi = sAlo + A_ELEMS;
        __nv_bfloat16* sBlo = sBhi + B_ELEMS;
#pragma unroll
        for (int i = 0; i < 2; i++) {
            const int c   = tid + 256 * i;
            const int ar  = c >> 2;           // 0..127
            const int akc = c & 3;            // k chunk of 8
            const size_t asrc = (size_t)ar * Kdim + kt + akc * 8;
            cp16(smem_u32(&sAhi[ar * AS_STRIDE + akc * 8]), Ahi_g + asrc);
            cp16(smem_u32(&sAlo[ar * AS_STRIDE + akc * 8]), Alo_g + asrc);

            const int br  = c >> 4;           // 0..31
            const int bnc = c & 15;           // n chunk of 8
            const size_t bsrc = (size_t)(kt + br) * Ndim + bnc * 8;
            cp16(smem_u32(&sBhi[br * BS_STRIDE + bnc * 8]), Bhi_g + bsrc);
            cp16(smem_u32(&sBlo[br * BS_STRIDE + bnc * 8]), Blo_g + bsrc);
        }
        asm volatile("cp.async.commit_group;\n" ::: "memory");
    };

    const int T = Kdim / BK;       // 32 (G1) or 128 (G2); always >= 3
    issue_stage(0, 0);
    issue_stage(1, BK);
    issue_stage(2, 2 * BK);

    for (int it = 0; it < T; it++) {
        // Groups issued so far: up to min(it+2, T-1). Groups newer than `it`
        // still allowed in flight: min(it+2, T-1) - it.
        if (it + 2 < T) {
            asm volatile("cp.async.wait_group 2;\n" ::: "memory");
        } else if (it + 1 < T) {
            asm volatile("cp.async.wait_group 1;\n" ::: "memory");
        } else {
            asm volatile("cp.async.wait_group 0;\n" ::: "memory");
        }
        __syncthreads();
        // Safe to issue into stage (it+3)%4 == (it-1)%4: the barrier above
        // ordered every warp's compute(it-1) before this point.
        if (it + 3 < T) issue_stage((it + 3) % NSTAGE, (it + 3) * BK);

        const int st = it % NSTAGE;
        const __nv_bfloat16* sAhi = smem + st * STAGE_ELEMS;
        const __nv_bfloat16* sAlo = sAhi + A_ELEMS;
        const __nv_bfloat16* sBhi = sAlo + A_ELEMS;
        const __nv_bfloat16* sBlo = sBhi + B_ELEMS;

#pragma unroll
        for (int s = 0; s < 2; s++) {
            const int kk = 16 * s;
            uint32_t ah[4][4], al[4][4], bh[4][2], bl[4][2];

#pragma unroll
            for (int mi = 0; mi < 4; mi++) {
                const int arow = wm + mi * 16 + (lane & 15);
                const int acol = kk + ((lane >> 4) << 3);
                ldmatrix_x4(ah[mi], smem_u32(&sAhi[arow * AS_STRIDE + acol]));
                ldmatrix_x4(al[mi], smem_u32(&sAlo[arow * AS_STRIDE + acol]));
            }
#pragma unroll
            for (int ni = 0; ni < 4; ni++) {
                const int brow = kk + (lane & 15);
                const int bcol = wn + ni * 8;
                ldmatrix_x2t(bh[ni], smem_u32(&sBhi[brow * BS_STRIDE + bcol]));
                ldmatrix_x2t(bl[ni], smem_u32(&sBlo[brow * BS_STRIDE + bcol]));
            }

#pragma unroll
            for (int ni = 0; ni < 4; ni++) {
#pragma unroll
                for (int mi = 0; mi < 4; mi++) mma_bf16(acc[mi][ni], ah[mi], bh[ni]);
#pragma unroll
                for (int mi = 0; mi < 4; mi++) mma_bf16(acc[mi][ni], ah[mi], bl[ni]);
#pragma unroll
                for (int mi = 0; mi < 4; mi++) mma_bf16(acc[mi][ni], al[mi], bh[ni]);
            }
        }
    }

    // -------- epilogue --------
    const float* be = bias + (size_t)e * Ndim;
#pragma unroll
    for (int ni = 0; ni < 4; ni++) {
        const int col = bn + wn + ni * 8 + 2 * tig;     // even -> 4B aligned pairs
        const float b0 = be[col], b1 = be[col + 1];
#pragma unroll
        for (int mi = 0; mi < 4; mi++) {
            const int row0 = bm + wm + mi * 16 + gid;
            const int row1 = row0 + 8;
            float v00 = acc[mi][ni][0] + b0;
            float v01 = acc[mi][ni][1] + b1;
            float v10 = acc[mi][ni][2] + b0;
            float v11 = acc[mi][ni][3] + b1;
            if (G1) {
                v00 = gelu_exact(v00); v01 = gelu_exact(v01);
                v10 = gelu_exact(v10); v11 = gelu_exact(v11);
                __nv_bfloat16 ha, la, hb, lb;
                split_bf16(v00, ha, la); split_bf16(v01, hb, lb);
                const uint32_t h01 = pack2(ha, hb), l01 = pack2(la, lb);
                split_bf16(v10, ha, la); split_bf16(v11, hb, lb);
                const uint32_t h23 = pack2(ha, hb), l23 = pack2(la, lb);
                const size_t o0 = ((size_t)e * M_ + row0) * F_ + col;
                const size_t o1 = ((size_t)e * M_ + row1) * F_ + col;
                *reinterpret_cast<uint32_t*>(Dhi + o0) = h01;
                *reinterpret_cast<uint32_t*>(Dlo + o0) = l01;
                *reinterpret_cast<uint32_t*>(Dhi + o1) = h23;
                *reinterpret_cast<uint32_t*>(Dlo + o1) = l23;
            } else {
                const int g  = row0 >> 9;                // tile rows share g
                const int c0 = row0 & (C_ - 1);
                const int c1 = row1 & (C_ - 1);
                float* d0 = Dout + ((size_t)(g * E_ + e) * C_ + c0) * H_ + col;
                float* d1 = Dout + ((size_t)(g * E_ + e) * C_ + c1) * H_ + col;
                *reinterpret_cast<float2*>(d0) = make_float2(v00, v01);
                *reinterpret_cast<float2*>(d1) = make_float2(v10, v11);
            }
        }
    }
}

extern "C" void kernel_launch(void* const* d_in, const int* in_sizes, int n_in,
                              void* d_out, int out_size) {
    const float* inputs = (const float*)d_in[0];  // (G,E,C,H)
    const float* wi     = (const float*)d_in[1];  // (E,H,F)
    const float* bi     = (const float*)d_in[2];  // (E,F)
    const float* wo     = (const float*)d_in[3];  // (E,F,H)
    const float* bo     = (const float*)d_in[4];  // (E,H)
    float*       out    = (float*)d_out;          // (G,E,C,H)
    (void)in_sizes; (void)n_in; (void)out_size;

    __nv_bfloat16 *in_hi, *in_lo, *wi_hi, *wi_lo, *wo_hi, *wo_lo, *scr_hi, *scr_lo;
    cudaGetSymbolAddress((void**)&in_hi, g_in_hi);
    cudaGetSymbolAddress((void**)&in_lo, g_in_lo);
    cudaGetSymbolAddress((void**)&wi_hi, g_wi_hi);
    cudaGetSymbolAddress((void**)&wi_lo, g_wi_lo);
    cudaGetSymbolAddress((void**)&wo_hi, g_wo_hi);
    cudaGetSymbolAddress((void**)&wo_lo, g_wo_lo);
    cudaGetSymbolAddress((void**)&scr_hi, g_scr_hi);
    cudaGetSymbolAddress((void**)&scr_lo, g_scr_lo);

    // Raise dynamic smem cap (host attribute set; capture-safe, idempotent)
    cudaFuncSetAttribute(ffn_mma<true >, cudaFuncAttributeMaxDynamicSharedMemorySize, SMEM_BYTES);
    cudaFuncSetAttribute(ffn_mma<false>, cudaFuncAttributeMaxDynamicSharedMemorySize, SMEM_BYTES);

    // ---- pre-split fp32 -> bf16 hi/lo ----
    const int n4_in = (G_ * E_ * C_ * H_) / 4;     // 8,388,608 float4
    const int n4_wi = (E_ * H_ * F_) / 4;          // 8,388,608 float4
    const int n4_wo = (E_ * F_ * H_) / 4;          // 8,388,608 float4
    split_kernel<<<(n4_in + 255) / 256, 256>>>((const float4*)inputs, (uint2*)in_hi, (uint2*)in_lo, n4_in);
    split_kernel<<<(n4_wi + 255) / 256, 256>>>((const float4*)wi,     (uint2*)wi_hi, (uint2*)wi_lo, n4_wi);
    split_kernel<<<(n4_wo + 255) / 256, 256>>>((const float4*)wo,     (uint2*)wo_hi, (uint2*)wo_lo, n4_wo);

    dim3 grid1(F_ / BN, M_ / BM, E_);   // 32 x 32 x 8
    dim3 grid2(H_ / BN, M_ / BM, E_);   //  8 x 32 x 8
    ffn_mma<true ><<<grid1, 256, SMEM_BYTES>>>(in_hi, in_lo, wi_hi, wi_lo, bi,
                                               nullptr, scr_hi, scr_lo, H_, F_);
    ffn_mma<false><<<grid2, 256, SMEM_BYTES>>>(scr_hi, scr_lo, wo_hi, wo_lo, bo,
                                               out, nullptr, nullptr, F_, H_);
}

// round 17
// speedup vs baseline: 1.2110x; 1.2110x over previous
#include <cuda_runtime.h>
#include <cuda_bf16.h>
#include <math.h>
#include <stdint.h>

// Problem shapes (fixed)
#define G_  8
#define E_  8
#define C_  512
#define H_  1024
#define F_  4096
#define M_  (G_ * C_)    // 4096 rows per expert

#define BM 128
#define BN 128
#define BK 32
#define AS_STRIDE (BK + 8)   // 40 bf16 = 80B rows  -> ldmatrix conflict-free
#define BS_STRIDE (BN + 8)   // 136 bf16 = 272B rows -> ldmatrix conflict-free

#define A_ELEMS     (BM * AS_STRIDE)              // 5120 bf16
#define B_ELEMS     (BK * BS_STRIDE)              // 4352 bf16
#define STAGE_ELEMS (2 * A_ELEMS + 2 * B_ELEMS)   // 18944 bf16 = 37888 B
#define NSTAGE      2
#define SMEM_BYTES  (NSTAGE * STAGE_ELEMS * 2)    // 75776 B -> 2 CTAs/SM

// ---- pre-split global operands (static device scratch; no cudaMalloc) ----
__device__ __align__(16) __nv_bfloat16 g_in_hi[(size_t)G_ * E_ * C_ * H_];
__device__ __align__(16) __nv_bfloat16 g_in_lo[(size_t)G_ * E_ * C_ * H_];
__device__ __align__(16) __nv_bfloat16 g_wi_hi[(size_t)E_ * H_ * F_];
__device__ __align__(16) __nv_bfloat16 g_wi_lo[(size_t)E_ * H_ * F_];
__device__ __align__(16) __nv_bfloat16 g_wo_hi[(size_t)E_ * F_ * H_];
__device__ __align__(16) __nv_bfloat16 g_wo_lo[(size_t)E_ * F_ * H_];
__device__ __align__(16) __nv_bfloat16 g_scr_hi[(size_t)E_ * M_ * F_];
__device__ __align__(16) __nv_bfloat16 g_scr_lo[(size_t)E_ * M_ * F_];

__device__ __forceinline__ float gelu_exact(float x) {
    return 0.5f * x * (1.0f + erff(x * 0.70710678118654752440f));
}

__device__ __forceinline__ uint32_t pack2(__nv_bfloat16 a, __nv_bfloat16 b) {
    __nv_bfloat162 t = __halves2bfloat162(a, b);
    return *reinterpret_cast<uint32_t*>(&t);
}

__device__ __forceinline__ void split_bf16(float x, __nv_bfloat16& h, __nv_bfloat16& l) {
    h = __float2bfloat16_rn(x);
    l = __float2bfloat16_rn(x - __bfloat162float(h));
}

__device__ __forceinline__ uint32_t smem_u32(const void* p) {
    return (uint32_t)__cvta_generic_to_shared(p);
}

__device__ __forceinline__ void cp16(uint32_t dst, const void* src) {
    asm volatile("cp.async.cg.shared.global [%0], [%1], 16;\n" :: "r"(dst), "l"(src));
}

__device__ __forceinline__ void ldmatrix_x4(uint32_t* r, uint32_t addr) {
    asm volatile("ldmatrix.sync.aligned.m8n8.x4.shared.b16 {%0,%1,%2,%3}, [%4];"
                 : "=r"(r[0]), "=r"(r[1]), "=r"(r[2]), "=r"(r[3]) : "r"(addr));
}

__device__ __forceinline__ void ldmatrix_x2t(uint32_t* r, uint32_t addr) {
    asm volatile("ldmatrix.sync.aligned.m8n8.x2.trans.shared.b16 {%0,%1}, [%2];"
                 : "=r"(r[0]), "=r"(r[1]) : "r"(addr));
}

__device__ __forceinline__ void mma_bf16(float* d, const uint32_t* a, const uint32_t* b) {
    asm volatile(
        "mma.sync.aligned.m16n8k16.row.col.f32.bf16.bf16.f32 "
        "{%0,%1,%2,%3}, {%4,%5,%6,%7}, {%8,%9}, {%0,%1,%2,%3};\n"
        : "+f"(d[0]), "+f"(d[1]), "+f"(d[2]), "+f"(d[3])
        : "r"(a[0]), "r"(a[1]), "r"(a[2]), "r"(a[3]),
          "r"(b[0]), "r"(b[1]));
}

// ---------------------------------------------------------------------------
// Pre-split: fp32 -> (hi, lo) bf16 arrays, vectorized x4.
// ---------------------------------------------------------------------------
__global__ __launch_bounds__(256)
void split_kernel(const float4* __restrict__ src,
                  uint2* __restrict__ hi, uint2* __restrict__ lo, int n4)
{
    int i = blockIdx.x * blockDim.x + threadIdx.x;
    if (i >= n4) return;
    float4 v = src[i];
    __nv_bfloat16 h0, h1, h2, h3, l0, l1, l2, l3;
    split_bf16(v.x, h0, l0); split_bf16(v.y, h1, l1);
    split_bf16(v.z, h2, l2); split_bf16(v.w, h3, l3);
    hi[i] = make_uint2(pack2(h0, h1), pack2(h2, h3));
    lo[i] = make_uint2(pack2(l0, l1), pack2(l2, l3));
}

// ---------------------------------------------------------------------------
// bf16x3 GEMM on pre-split operands, 2-stage cp.async pipeline, 2 CTAs/SM:
//   D[M,N] = A[M,K] @ B[K,N] (+bias; G1: exact GELU + split-store to scratch)
// ---------------------------------------------------------------------------
template<bool G1>
__global__ __launch_bounds__(256, 2)
void ffn_mma(const __nv_bfloat16* __restrict__ Ahi_g0,
             const __nv_bfloat16* __restrict__ Alo_g0,
             const __nv_bfloat16* __restrict__ Bhi_g0,
             const __nv_bfloat16* __restrict__ Blo_g0,
             const float* __restrict__ bias,
             float* __restrict__ Dout,          // G2 only
             __nv_bfloat16* __restrict__ Dhi,   // G1 only
             __nv_bfloat16* __restrict__ Dlo,   // G1 only
             int Kdim, int Ndim)
{
    extern __shared__ __nv_bfloat16 smem[];

    const int e   = blockIdx.z;
    const int bm  = blockIdx.y * BM;
    const int bn  = blockIdx.x * BN;
    const int tid = threadIdx.x;
    const int lane = tid & 31;
    const int wid  = tid >> 5;
    const int gid  = lane >> 2;
    const int tig  = lane & 3;

    // A base pointers for this CTA's 128 rows (row stride = Kdim)
    size_t a_off;
    if (G1) {
        const int g = bm >> 9;            // / C_
        const int c = bm & (C_ - 1);
        a_off = ((size_t)(g * E_ + e) * C_ + c) * Kdim;
    } else {
        a_off = ((size_t)e * M_ + bm) * (size_t)Kdim;
    }
    const __nv_bfloat16* Ahi_g = Ahi_g0 + a_off;
    const __nv_bfloat16* Alo_g = Alo_g0 + a_off;
    const size_t b_off = (size_t)e * Kdim * Ndim + bn;
    const __nv_bfloat16* Bhi_g = Bhi_g0 + b_off;
    const __nv_bfloat16* Blo_g = Blo_g0 + b_off;

    // warp tile: 2 (M) x 4 (N) warps, 64x32 each
    const int wm = (wid >> 2) * 64;
    const int wn = (wid & 3) * 32;

    float acc[4][4][4];
#pragma unroll
    for (int i = 0; i < 4; i++)
#pragma unroll
        for (int j = 0; j < 4; j++)
#pragma unroll
            for (int k = 0; k < 4; k++) acc[i][j][k] = 0.0f;

    // cp.async loader: 16B chunks (8 bf16). Per stage: A = 512 chunks
    // (128 rows x 4 k-chunks), B = 512 chunks (32 rows x 16 n-chunks).
    auto issue_stage = [&](int st, int kt) {
        __nv_bfloat16* sAhi = smem + st * STAGE_ELEMS;
        __nv_bfloat16* sAlo = sAhi + A_ELEMS;
        __nv_bfloat16* sBhi = sAlo + A_ELEMS;
        __nv_bfloat16* sBlo = sBhi + B_ELEMS;
#pragma unroll
        for (int i = 0; i < 2; i++) {
            const int c   = tid + 256 * i;
            const int ar  = c >> 2;           // 0..127
            const int akc = c & 3;            // k chunk of 8
            const size_t asrc = (size_t)ar * Kdim + kt + akc * 8;
            cp16(smem_u32(&sAhi[ar * AS_STRIDE + akc * 8]), Ahi_g + asrc);
            cp16(smem_u32(&sAlo[ar * AS_STRIDE + akc * 8]), Alo_g + asrc);

            const int br  = c >> 4;           // 0..31
            const int bnc = c & 15;           // n chunk of 8
            const size_t bsrc = (size_t)(kt + br) * Ndim + bnc * 8;
            cp16(smem_u32(&sBhi[br * BS_STRIDE + bnc * 8]), Bhi_g + bsrc);
            cp16(smem_u32(&sBlo[br * BS_STRIDE + bnc * 8]), Blo_g + bsrc);
        }
        asm volatile("cp.async.commit_group;\n" ::: "memory");
    };

    const int T = Kdim / BK;       // 32 (G1) or 128 (G2)
    issue_stage(0, 0);

    for (int it = 0; it < T; it++) {
        // Only pending group here is `it` (group it+1 not yet issued).
        asm volatile("cp.async.wait_group 0;\n" ::: "memory");
        __syncthreads();
        // Barrier ordered every warp's compute(it-1); stage (it+1)%2 is free.
        if (it + 1 < T) issue_stage((it + 1) & 1, (it + 1) * BK);

        const int st = it & 1;
        const __nv_bfloat16* sAhi = smem + st * STAGE_ELEMS;
        const __nv_bfloat16* sAlo = sAhi + A_ELEMS;
        const __nv_bfloat16* sBhi = sAlo + A_ELEMS;
        const __nv_bfloat16* sBlo = sBhi + B_ELEMS;

#pragma unroll
        for (int s = 0; s < 2; s++) {
            const int kk = 16 * s;
            // B fragments for all 4 ni (16 regs live)
            uint32_t bh[4][2], bl[4][2];
#pragma unroll
            for (int ni = 0; ni < 4; ni++) {
                const int brow = kk + (lane & 15);
                const int bcol = wn + ni * 8;
                ldmatrix_x2t(bh[ni], smem_u32(&sBhi[brow * BS_STRIDE + bcol]));
                ldmatrix_x2t(bl[ni], smem_u32(&sBlo[brow * BS_STRIDE + bcol]));
            }
            // Per-mi A fragments (8 regs live), 12 MMAs each
#pragma unroll
            for (int mi = 0; mi < 4; mi++) {
                const int arow = wm + mi * 16 + (lane & 15);
                const int acol = kk + ((lane >> 4) << 3);
                uint32_t ah[4], al[4];
                ldmatrix_x4(ah, smem_u32(&sAhi[arow * AS_STRIDE + acol]));
                ldmatrix_x4(al, smem_u32(&sAlo[arow * AS_STRIDE + acol]));
#pragma unroll
                for (int ni = 0; ni < 4; ni++) mma_bf16(acc[mi][ni], ah, bh[ni]);
#pragma unroll
                for (int ni = 0; ni < 4; ni++) mma_bf16(acc[mi][ni], ah, bl[ni]);
#pragma unroll
                for (int ni = 0; ni < 4; ni++) mma_bf16(acc[mi][ni], al, bh[ni]);
            }
        }
    }

    // -------- epilogue --------
    const float* be = bias + (size_t)e * Ndim;
#pragma unroll
    for (int ni = 0; ni < 4; ni++) {
        const int col = bn + wn + ni * 8 + 2 * tig;     // even -> 4B aligned pairs
        const float b0 = be[col], b1 = be[col + 1];
#pragma unroll
        for (int mi = 0; mi < 4; mi++) {
            const int row0 = bm + wm + mi * 16 + gid;
            const int row1 = row0 + 8;
            float v00 = acc[mi][ni][0] + b0;
            float v01 = acc[mi][ni][1] + b1;
            float v10 = acc[mi][ni][2] + b0;
            float v11 = acc[mi][ni][3] + b1;
            if (G1) {
                v00 = gelu_exact(v00); v01 = gelu_exact(v01);
                v10 = gelu_exact(v10); v11 = gelu_exact(v11);
                __nv_bfloat16 ha, la, hb, lb;
                split_bf16(v00, ha, la); split_bf16(v01, hb, lb);
                const uint32_t h01 = pack2(ha, hb), l01 = pack2(la, lb);
                split_bf16(v10, ha, la); split_bf16(v11, hb, lb);
                const uint32_t h23 = pack2(ha, hb), l23 = pack2(la, lb);
                const size_t o0 = ((size_t)e * M_ + row0) * F_ + col;
                const size_t o1 = ((size_t)e * M_ + row1) * F_ + col;
                *reinterpret_cast<uint32_t*>(Dhi + o0) = h01;
                *reinterpret_cast<uint32_t*>(Dlo + o0) = l01;
                *reinterpret_cast<uint32_t*>(Dhi + o1) = h23;
                *reinterpret_cast<uint32_t*>(Dlo + o1) = l23;
            } else {
                const int g  = row0 >> 9;                // tile rows share g
                const int c0 = row0 & (C_ - 1);
                const int c1 = row1 & (C_ - 1);
                float* d0 = Dout + ((size_t)(g * E_ + e) * C_ + c0) * H_ + col;
                float* d1 = Dout + ((size_t)(g * E_ + e) * C_ + c1) * H_ + col;
                *reinterpret_cast<float2*>(d0) = make_float2(v00, v01);
                *reinterpret_cast<float2*>(d1) = make_float2(v10, v11);
            }
        }
    }
}

extern "C" void kernel_launch(void* const* d_in, const int* in_sizes, int n_in,
                              void* d_out, int out_size) {
    const float* inputs = (const float*)d_in[0];  // (G,E,C,H)
    const float* wi     = (const float*)d_in[1];  // (E,H,F)
    const float* bi     = (const float*)d_in[2];  // (E,F)
    const float* wo     = (const float*)d_in[3];  // (E,F,H)
    const float* bo     = (const float*)d_in[4];  // (E,H)
    float*       out    = (float*)d_out;          // (G,E,C,H)
    (void)in_sizes; (void)n_in; (void)out_size;

    __nv_bfloat16 *in_hi, *in_lo, *wi_hi, *wi_lo, *wo_hi, *wo_lo, *scr_hi, *scr_lo;
    cudaGetSymbolAddress((void**)&in_hi, g_in_hi);
    cudaGetSymbolAddress((void**)&in_lo, g_in_lo);
    cudaGetSymbolAddress((void**)&wi_hi, g_wi_hi);
    cudaGetSymbolAddress((void**)&wi_lo, g_wi_lo);
    cudaGetSymbolAddress((void**)&wo_hi, g_wo_hi);
    cudaGetSymbolAddress((void**)&wo_lo, g_wo_lo);
    cudaGetSymbolAddress((void**)&scr_hi, g_scr_hi);
    cudaGetSymbolAddress((void**)&scr_lo, g_scr_lo);

    // Raise dynamic smem cap (host attribute set; capture-safe, idempotent)
    cudaFuncSetAttribute(ffn_mma<true >, cudaFuncAttributeMaxDynamicSharedMemorySize, SMEM_BYTES);
    cudaFuncSetAttribute(ffn_mma<false>, cudaFuncAttributeMaxDynamicSharedMemorySize, SMEM_BYTES);

    // ---- pre-split fp32 -> bf16 hi/lo ----
    const int n4_in = (G_ * E_ * C_ * H_) / 4;     // 8,388,608 float4
    const int n4_wi = (E_ * H_ * F_) / 4;          // 8,388,608 float4
    const int n4_wo = (E_ * F_ * H_) / 4;          // 8,388,608 float4
    split_kernel<<<(n4_in + 255) / 256, 256>>>((const float4*)inputs, (uint2*)in_hi, (uint2*)in_lo, n4_in);
    split_kernel<<<(n4_wi + 255) / 256, 256>>>((const float4*)wi,     (uint2*)wi_hi, (uint2*)wi_lo, n4_wi);
    split_kernel<<<(n4_wo + 255) / 256, 256>>>((const float4*)wo,     (uint2*)wo_hi, (uint2*)wo_lo, n4_wo);

    dim3 grid1(F_ / BN, M_ / BM, E_);   // 32 x 32 x 8
    dim3 grid2(H_ / BN, M_ / BM, E_);   //  8 x 32 x 8
    ffn_mma<true ><<<grid1, 256, SMEM_BYTES>>>(in_hi, in_lo, wi_hi, wi_lo, bi,
                                               nullptr, scr_hi, scr_lo, H_, F_);
    ffn_mma<false><<<grid2, 256, SMEM_BYTES>>>(scr_hi, scr_lo, wo_hi, wo_lo, bo,
                                               out, nullptr, nullptr, F_, H_);
}